// round 1
// baseline (speedup 1.0000x reference)
#include <cuda_runtime.h>
#include <cstdint>
#include <cstddef>

// Problem dims
#define Bc 256
#define Tc 128
#define Hc 1024
#define Vc 64
#define Lc 457
#define ML 64

// GEMM tiling
#define BM 32
#define BN 64
#define BK 16
#define NT 256

// ---------------- device scratch (no allocs allowed) ----------------
__device__ float g_U0[Bc * Tc * Hc];     // x @ enc_Wih0^T + b0, row m = b*T + t
__device__ float g_h0[2][Bc * Hc];       // encoder layer0 ping-pong
__device__ float g_h1[2][Bc * Hc];       // encoder layer1 ping-pong
__device__ float g_d0[2][Bc * Hc];       // decoder layer0 ping-pong
__device__ float g_d1[2][Bc * Hc];       // decoder layer1 ping-pong
__device__ float g_zero[Bc * Hc];        // zero initial hidden state
__device__ int   g_tok[Bc];              // current decoder tokens

// ---------------- helpers ----------------

__device__ __forceinline__ void load_tile(
    const float* __restrict__ A, size_t lda, const int* __restrict__ gather,
    const float* __restrict__ W, int K,
    int m0, int n0, int k0, int tid, float a_r[2], float w_r[4])
{
    // A tile: BM x BK = 512 elements, 2 per thread
#pragma unroll
    for (int i = 0; i < 2; i++) {
        int e = tid * 2 + i;
        int row = e >> 4;      // / BK
        int kk = e & 15;
        int kg = k0 + kk;
        size_t arow = gather ? (size_t)__ldg(&gather[m0 + row]) : (size_t)(m0 + row);
        a_r[i] = (kg < K) ? A[arow * lda + (size_t)kg] : 0.0f;
    }
    // W tile: BN x BK = 1024 elements, 4 per thread (contiguous in K)
    int wrow = tid >> 2;            // 0..63
    int wk = (tid & 3) * 4;         // 0,4,8,12
    const float* wp = W + (size_t)(n0 + wrow) * (size_t)K + (size_t)(k0 + wk);
    if ((k0 + wk + 3 < K) && ((((uintptr_t)wp) & 15u) == 0)) {
        float4 v = *(const float4*)wp;
        w_r[0] = v.x; w_r[1] = v.y; w_r[2] = v.z; w_r[3] = v.w;
    } else {
#pragma unroll
        for (int i = 0; i < 4; i++) {
            int kg = k0 + wk + i;
            w_r[i] = (kg < K) ? wp[i] : 0.0f;
        }
    }
}

__device__ __forceinline__ void store_tile(
    float As[BK][BM], float Ws[BK][BN],
    int tid, const float a_r[2], const float w_r[4])
{
#pragma unroll
    for (int i = 0; i < 2; i++) {
        int e = tid * 2 + i;
        As[e & 15][e >> 4] = a_r[i];
    }
    int wrow = tid >> 2;
    int wk = (tid & 3) * 4;
#pragma unroll
    for (int i = 0; i < 4; i++) Ws[wk + i][wrow] = w_r[i];
}

__device__ __forceinline__ void mac_tile(
    float acc[2][4], const float As[BK][BM], const float Ws[BK][BN],
    int r0, int c0)
{
#pragma unroll
    for (int k = 0; k < BK; k++) {
        float2 a = *(const float2*)&As[k][r0];
        float4 w = *(const float4*)&Ws[k][c0];
        acc[0][0] += a.x * w.x; acc[0][1] += a.x * w.y;
        acc[0][2] += a.x * w.z; acc[0][3] += a.x * w.w;
        acc[1][0] += a.y * w.x; acc[1][1] += a.y * w.y;
        acc[1][2] += a.y * w.z; acc[1][3] += a.y * w.w;
    }
}

__device__ __forceinline__ void gemm_pair(
    float acc[2][4],
    const float* __restrict__ A, size_t lda,
    const float* __restrict__ W, int K,
    const int* __restrict__ gather,
    int m0, int n0, int tid, int r0, int c0,
    float As[2][BK][BM], float Ws[2][BK][BN])
{
    int nkb = (K + BK - 1) / BK;
    float a_r[2], w_r[4];
    load_tile(A, lda, gather, W, K, m0, n0, 0, tid, a_r, w_r);
    store_tile(As[0], Ws[0], tid, a_r, w_r);
    __syncthreads();
    int buf = 0;
    for (int kb = 0; kb < nkb; kb++) {
        bool hn = (kb + 1 < nkb);
        float na[2], nw[4];
        if (hn) load_tile(A, lda, gather, W, K, m0, n0, (kb + 1) * BK, tid, na, nw);
        mac_tile(acc, As[buf], Ws[buf], r0, c0);
        if (hn) store_tile(As[buf ^ 1], Ws[buf ^ 1], tid, na, nw);
        __syncthreads();
        buf ^= 1;
    }
}

// C[m,n] = act( A1[m,:]·W1[n,:] (+ A2[m,:]·W2[n,:]) (+ bias[n]) (+ addmat[m,n]) )
// A rows optionally gathered (embedding lookup). M = gridDim.y*BM, N = gridDim.x*BN.
__global__ void __launch_bounds__(NT)
rnn_gemm_kernel(const float* __restrict__ A1, size_t lda1,
                const float* __restrict__ W1, int K1,
                const int* __restrict__ gather,
                const float* __restrict__ A2, size_t lda2,
                const float* __restrict__ W2, int K2,
                const float* __restrict__ bias,
                const float* __restrict__ addmat, size_t ldadd,
                float* __restrict__ C, size_t ldc, int do_tanh)
{
    __shared__ float As[2][BK][BM];
    __shared__ float Ws[2][BK][BN];
    int tid = threadIdx.x;
    int m0 = blockIdx.y * BM;
    int n0 = blockIdx.x * BN;
    int r0 = (tid >> 4) * 2;
    int c0 = (tid & 15) * 4;
    float acc[2][4] = {{0.f, 0.f, 0.f, 0.f}, {0.f, 0.f, 0.f, 0.f}};

    gemm_pair(acc, A1, lda1, W1, K1, gather, m0, n0, tid, r0, c0, As, Ws);
    if (A2) gemm_pair(acc, A2, lda2, W2, K2, nullptr, m0, n0, tid, r0, c0, As, Ws);

#pragma unroll
    for (int i = 0; i < 2; i++) {
        int m = m0 + r0 + i;
#pragma unroll
        for (int j = 0; j < 4; j++) {
            int n = n0 + c0 + j;
            float v = acc[i][j];
            if (bias)   v += bias[n];
            if (addmat) v += addmat[(size_t)m * ldadd + (size_t)n];
            if (do_tanh) v = tanhf(v);
            C[(size_t)m * ldc + (size_t)n] = v;
        }
    }
}

// logits[b,v] = d1[b,:]·fcW[v,:] + fcb[v]; write to out[b,v,step]; tok[b] = argmax_v
__global__ void __launch_bounds__(Vc)
logits_argmax_kernel(const float* __restrict__ d1,
                     const float* __restrict__ fcW,
                     const float* __restrict__ fcb,
                     float* __restrict__ out, int step,
                     int* __restrict__ tok)
{
    int b = blockIdx.x;
    int v = threadIdx.x;
    const float4* hp = (const float4*)(d1 + (size_t)b * Hc);
    const float4* wp = (const float4*)(fcW + (size_t)v * Hc);
    float s = 0.0f;
#pragma unroll 8
    for (int i = 0; i < Hc / 4; i++) {
        float4 h4 = hp[i], w4 = wp[i];
        s += h4.x * w4.x + h4.y * w4.y + h4.z * w4.z + h4.w * w4.w;
    }
    s += fcb[v];
    out[((size_t)b * Vc + (size_t)v) * ML + (size_t)step] = s;

    __shared__ float vals[Vc];
    vals[v] = s;
    __syncthreads();
    if (v == 0) {
        float best = vals[0];
        int bi = 0;
#pragma unroll
        for (int i = 1; i < Vc; i++) {
            if (vals[i] > best) { best = vals[i]; bi = i; }  // first-max, matches jnp.argmax
        }
        tok[b] = bi;
    }
}

__global__ void init_kernel(float* __restrict__ z, int* __restrict__ tok)
{
    int i = blockIdx.x * blockDim.x + threadIdx.x;
    if (i < Bc * Hc) z[i] = 0.0f;
    if (i < Bc) tok[i] = 0;
}

__global__ void copy_hidden_kernel(const float* __restrict__ d0,
                                   const float* __restrict__ d1,
                                   float* __restrict__ o)
{
    int i = blockIdx.x * blockDim.x + threadIdx.x;
    if (i < Bc * Hc) {
        o[i] = d0[i];
        o[Bc * Hc + i] = d1[i];
    }
}

// ---------------- host ----------------

extern "C" void kernel_launch(void* const* d_in, const int* in_sizes, int n_in,
                              void* d_out, int out_size)
{
    (void)in_sizes; (void)n_in; (void)out_size;
    const float* x     = (const float*)d_in[0];
    const float* emb   = (const float*)d_in[1];
    const float* eWih0 = (const float*)d_in[2];
    const float* eWhh0 = (const float*)d_in[3];
    const float* eb0   = (const float*)d_in[4];
    const float* eWih1 = (const float*)d_in[5];
    const float* eWhh1 = (const float*)d_in[6];
    const float* eb1   = (const float*)d_in[7];
    const float* dWih0 = (const float*)d_in[8];
    const float* dWhh0 = (const float*)d_in[9];
    const float* db0   = (const float*)d_in[10];
    const float* dWih1 = (const float*)d_in[11];
    const float* dWhh1 = (const float*)d_in[12];
    const float* db1   = (const float*)d_in[13];
    const float* fcW   = (const float*)d_in[14];
    const float* fcb   = (const float*)d_in[15];
    float* out = (float*)d_out;

    float *U0, *h0base, *h1base, *d0base, *d1base, *zero;
    int* tok;
    cudaGetSymbolAddress((void**)&U0, g_U0);
    cudaGetSymbolAddress((void**)&h0base, g_h0);
    cudaGetSymbolAddress((void**)&h1base, g_h1);
    cudaGetSymbolAddress((void**)&d0base, g_d0);
    cudaGetSymbolAddress((void**)&d1base, g_d1);
    cudaGetSymbolAddress((void**)&zero, g_zero);
    cudaGetSymbolAddress((void**)&tok, g_tok);

    float* h0b[2] = { h0base, h0base + (size_t)Bc * Hc };
    float* h1b[2] = { h1base, h1base + (size_t)Bc * Hc };
    float* d0b[2] = { d0base, d0base + (size_t)Bc * Hc };
    float* d1b[2] = { d1base, d1base + (size_t)Bc * Hc };

    init_kernel<<<(Bc * Hc + 255) / 256, 256>>>(zero, tok);

    dim3 blk(NT);
    dim3 grid_step(Hc / BN, Bc / BM);            // 16 x 8 = 128 blocks
    dim3 grid_pre(Hc / BN, (Bc * Tc) / BM);      // 16 x 1024

    // U0[m= b*T+t, :] = x_flat[m,:] @ eWih0^T + b0   (parallel over all timesteps)
    rnn_gemm_kernel<<<grid_pre, blk>>>(
        x, (size_t)Lc, eWih0, Lc, nullptr,
        nullptr, 0, nullptr, 0,
        eb0, nullptr, 0,
        U0, (size_t)Hc, 0);

    // ---- encoder: sequential over T ----
    for (int t = 0; t < Tc; t++) {
        const float* h0prev = (t == 0) ? zero : h0b[(t + 1) & 1];
        float* h0cur = h0b[t & 1];
        // h0 = tanh(U0[:,t,:] + h0prev @ eWhh0^T)
        rnn_gemm_kernel<<<grid_step, blk>>>(
            h0prev, (size_t)Hc, eWhh0, Hc, nullptr,
            nullptr, 0, nullptr, 0,
            nullptr, U0 + (size_t)t * Hc, (size_t)Tc * Hc,
            h0cur, (size_t)Hc, 1);

        const float* h1prev = (t == 0) ? zero : h1b[(t + 1) & 1];
        float* h1cur = h1b[t & 1];
        // h1 = tanh(h0cur @ eWih1^T + h1prev @ eWhh1^T + b1)
        rnn_gemm_kernel<<<grid_step, blk>>>(
            h0cur, (size_t)Hc, eWih1, Hc, nullptr,
            h1prev, (size_t)Hc, eWhh1, Hc,
            eb1, nullptr, 0,
            h1cur, (size_t)Hc, 1);
    }

    // ---- decoder: greedy autoregressive ----
    const float* d0prev = h0b[(Tc - 1) & 1];   // encoder final layer0 state
    const float* d1prev = h1b[(Tc - 1) & 1];   // encoder final layer1 state
    for (int s = 0; s < ML; s++) {
        float* d0cur = d0b[s & 1];
        float* d1cur = d1b[s & 1];
        // d0 = tanh(emb[tok] @ dWih0^T + d0prev @ dWhh0^T + b0)
        rnn_gemm_kernel<<<grid_step, blk>>>(
            emb, (size_t)Hc, dWih0, Hc, tok,
            d0prev, (size_t)Hc, dWhh0, Hc,
            db0, nullptr, 0,
            d0cur, (size_t)Hc, 1);
        // d1 = tanh(d0cur @ dWih1^T + d1prev @ dWhh1^T + b1)
        rnn_gemm_kernel<<<grid_step, blk>>>(
            d0cur, (size_t)Hc, dWih1, Hc, nullptr,
            d1prev, (size_t)Hc, dWhh1, Hc,
            db1, nullptr, 0,
            d1cur, (size_t)Hc, 1);
        // logits + argmax -> next token
        logits_argmax_kernel<<<Bc, Vc>>>(d1cur, fcW, fcb, out, s, tok);
        d0prev = d0cur;
        d1prev = d1cur;
    }

    // hidden = stack([d0_final, d1_final])
    copy_hidden_kernel<<<(Bc * Hc + 255) / 256, 256>>>(
        d0prev, d1prev, out + (size_t)Bc * Vc * ML);
}

// round 2
// speedup vs baseline: 1.3284x; 1.3284x over previous
#include <cuda_runtime.h>
#include <cstdint>
#include <cstddef>

// Problem dims
#define Bc 256
#define Tc 128
#define Hc 1024
#define Vc 64
#define Lc 457
#define ML 64

typedef unsigned long long ull;

// ---------------- device scratch (no allocs allowed) ----------------
__device__ float g_U0[(size_t)Bc * Tc * Hc];   // x @ enc_Wih0^T + b0, row m = b*T + t
__device__ float g_h0[2][Bc * Hc];
__device__ float g_h1[2][Bc * Hc];
__device__ float g_d0[2][Bc * Hc];
__device__ float g_d1[2][Bc * Hc];
__device__ float g_zero[Bc * Hc];
__device__ int   g_tok[Bc];

// ---------------- packed fp32 helpers (sm_103a f32x2) ----------------
__device__ __forceinline__ ull dup2(float a) {
    ull r;
    asm("mov.b64 %0, {%1, %1};" : "=l"(r) : "r"(__float_as_uint(a)));
    return r;
}
__device__ __forceinline__ void ffma2(ull& d, ull a, ull b) {
    asm("fma.rn.f32x2 %0, %1, %2, %0;" : "+l"(d) : "l"(a), "l"(b));
}
__device__ __forceinline__ void unpk(ull v, float& lo, float& hi) {
    unsigned int a, b;
    asm("mov.b64 {%0, %1}, %2;" : "=r"(a), "=r"(b) : "l"(v));
    lo = __uint_as_float(a);
    hi = __uint_as_float(b);
}

// ---------------- GEMM job descriptor ----------------
struct GemmJob {
    const float* A1; long lda1; const float* W1; int K1;
    const int* gather;
    const float* A2; long lda2; const float* W2; int K2;
    const float* bias; const float* addmat; long ldadd;
    float* C; long ldc; int act; int valid;
};

// ---------------- tile loaders ----------------
// Loads a BR x 16 tile (rows of A/W along K) into registers, float4 per chunk.
template<int NT, int BR>
__device__ __forceinline__ void load_tile(
    const float* __restrict__ A, long lda, const int* __restrict__ gather,
    int r_base, int K, int k0, int tid, float (&r)[BR * 4 / NT][4])
{
    constexpr int NC = BR * 4 / NT;
#pragma unroll
    for (int i = 0; i < NC; i++) {
        int cid = tid + i * NT;
        int row = cid >> 2, kq = cid & 3;
        int kk = k0 + kq * 4;
        long arow = gather ? (long)__ldg(&gather[r_base + row]) : (long)(r_base + row);
        const float* p = A + arow * lda + kk;
        if (kk + 3 < K && ((((uintptr_t)p) & 15u) == 0)) {
            float4 v = *(const float4*)p;
            r[i][0] = v.x; r[i][1] = v.y; r[i][2] = v.z; r[i][3] = v.w;
        } else {
#pragma unroll
            for (int j = 0; j < 4; j++)
                r[i][j] = (kk + j < K) ? __ldg(p + j) : 0.0f;
        }
    }
}

template<int NT, int BR>
__device__ __forceinline__ void store_tile(
    float (&S)[16][BR], int tid, const float (&r)[BR * 4 / NT][4])
{
    constexpr int NC = BR * 4 / NT;
#pragma unroll
    for (int i = 0; i < NC; i++) {
        int cid = tid + i * NT;
        int row = cid >> 2, kq = cid & 3;
#pragma unroll
        for (int j = 0; j < 4; j++)
            S[kq * 4 + j][row] = r[i][j];
    }
}

// ---------------- micro-kernel: TM x TN per thread via f32x2 ----------------
template<int BM, int BN, int TM, int TN>
__device__ __forceinline__ void mac_block(
    const float (&As)[16][BM], const float (&Ws)[16][BN],
    int r0, int c0, ull (&acc)[TM][TN / 2])
{
#pragma unroll
    for (int k = 0; k < 16; k++) {
        ull ad[TM];
#pragma unroll
        for (int i = 0; i < TM; i += 4) {
            float4 av = *(const float4*)&As[k][r0 + i];
            ad[i + 0] = dup2(av.x);
            ad[i + 1] = dup2(av.y);
            ad[i + 2] = dup2(av.z);
            ad[i + 3] = dup2(av.w);
        }
        ull wv[TN / 2];
#pragma unroll
        for (int p = 0; p < TN / 2; p += 2) {
            ulonglong2 w2 = *(const ulonglong2*)&Ws[k][c0 + 2 * p];
            wv[p] = w2.x;
            wv[p + 1] = w2.y;
        }
#pragma unroll
        for (int i = 0; i < TM; i++)
#pragma unroll
            for (int p = 0; p < TN / 2; p++)
                ffma2(acc[i][p], ad[i], wv[p]);
    }
}

// ---------------- one GEMM source (A @ W^T accumulation) ----------------
template<int NT, int BM, int BN, int TM, int TN>
__device__ __forceinline__ void gemm_source(
    const float* __restrict__ A, long lda,
    const float* __restrict__ W, int K,
    const int* __restrict__ gather,
    int m0, int n0, int tid, int r0, int c0,
    float (&As)[2][16][BM], float (&Ws)[2][16][BN],
    ull (&acc)[TM][TN / 2])
{
    constexpr int NCA = BM * 4 / NT;
    constexpr int NCW = BN * 4 / NT;
    float ar[NCA][4], wr[NCW][4];
    int nkb = (K + 15) / 16;

    load_tile<NT, BM>(A, lda, gather, m0, K, 0, tid, ar);
    load_tile<NT, BN>(W, (long)K, nullptr, n0, K, 0, tid, wr);
    store_tile<NT, BM>(As[0], tid, ar);
    store_tile<NT, BN>(Ws[0], tid, wr);
    __syncthreads();

    int buf = 0;
    for (int kb = 0; kb < nkb; kb++) {
        bool hn = (kb + 1 < nkb);
        if (hn) {
            load_tile<NT, BM>(A, lda, gather, m0, K, (kb + 1) * 16, tid, ar);
            load_tile<NT, BN>(W, (long)K, nullptr, n0, K, (kb + 1) * 16, tid, wr);
        }
        mac_block<BM, BN, TM, TN>(As[buf], Ws[buf], r0, c0, acc);
        if (hn) {
            store_tile<NT, BM>(As[buf ^ 1], tid, ar);
            store_tile<NT, BN>(Ws[buf ^ 1], tid, wr);
        }
        __syncthreads();
        buf ^= 1;
    }
}

// ---------------- generic GEMM kernel, up to 2 independent jobs via blockIdx.z ----------------
template<int NT, int BM, int BN, int TM, int TN>
__global__ void __launch_bounds__(NT)
gemm_kernel(GemmJob j0, GemmJob j1)
{
    GemmJob j = (blockIdx.z == 0) ? j0 : j1;
    if (!j.valid) return;

    __shared__ float As[2][16][BM];
    __shared__ float Ws[2][16][BN];

    constexpr int CT = BN / TN;
    int tid = threadIdx.x;
    int m0 = blockIdx.y * BM;
    int n0 = blockIdx.x * BN;
    int ty = tid / CT, tx = tid % CT;
    int r0 = ty * TM, c0 = tx * TN;

    ull acc[TM][TN / 2] = {};

    gemm_source<NT, BM, BN, TM, TN>(j.A1, j.lda1, j.W1, j.K1, j.gather,
                                    m0, n0, tid, r0, c0, As, Ws, acc);
    if (j.A2)
        gemm_source<NT, BM, BN, TM, TN>(j.A2, j.lda2, j.W2, j.K2, nullptr,
                                        m0, n0, tid, r0, c0, As, Ws, acc);

#pragma unroll
    for (int i = 0; i < TM; i++) {
        int m = m0 + r0 + i;
        float o[TN];
#pragma unroll
        for (int p = 0; p < TN / 2; p++)
            unpk(acc[i][p], o[2 * p], o[2 * p + 1]);
#pragma unroll
        for (int q = 0; q < TN; q++) {
            float v = o[q];
            int n = n0 + c0 + q;
            if (j.bias)   v += __ldg(&j.bias[n]);
            if (j.addmat) v += __ldg(&j.addmat[(long)m * j.ldadd + n]);
            if (j.act)    v = tanhf(v);
            o[q] = v;
        }
#pragma unroll
        for (int q = 0; q < TN; q += 4)
            *(float4*)&j.C[(long)m * j.ldc + n0 + c0 + q] = *(const float4*)&o[q];
    }
}

// ---------------- logits + argmax (decoder head) ----------------
__global__ void __launch_bounds__(256)
logits_kernel(const float* __restrict__ d1, const float* __restrict__ fcW,
              const float* __restrict__ fcb, float* __restrict__ out,
              int step, int* __restrict__ tok)
{
    __shared__ float hs[Hc];
    __shared__ float vals[Vc];
    int b = blockIdx.x, tid = threadIdx.x;

    *(float4*)&hs[tid * 4] = *(const float4*)&d1[(size_t)b * Hc + tid * 4];
    __syncthreads();

    int warp = tid >> 5, lane = tid & 31;
#pragma unroll
    for (int j = 0; j < 8; j++) {
        int v = warp * 8 + j;
        const float4* wp = (const float4*)&fcW[(size_t)v * Hc];
        float s = 0.0f;
#pragma unroll
        for (int i = 0; i < 8; i++) {
            float4 w4 = __ldg(&wp[lane + i * 32]);
            float4 h4 = *(const float4*)&hs[(lane + i * 32) * 4];
            s += w4.x * h4.x + w4.y * h4.y + w4.z * h4.z + w4.w * h4.w;
        }
#pragma unroll
        for (int o = 16; o; o >>= 1) s += __shfl_xor_sync(0xffffffffu, s, o);
        if (lane == 0) {
            s += fcb[v];
            vals[v] = s;
            out[((size_t)b * Vc + (size_t)v) * ML + (size_t)step] = s;
        }
    }
    __syncthreads();
    if (tid == 0) {
        float best = vals[0]; int bi = 0;
#pragma unroll
        for (int i = 1; i < Vc; i++)
            if (vals[i] > best) { best = vals[i]; bi = i; }   // first-max = jnp.argmax
        tok[b] = bi;
    }
}

__global__ void init_kernel(float* __restrict__ z, int* __restrict__ tok)
{
    int i = blockIdx.x * blockDim.x + threadIdx.x;
    if (i < Bc * Hc) z[i] = 0.0f;
    if (i < Bc) tok[i] = 0;
}

__global__ void copy_hidden_kernel(const float* __restrict__ d0,
                                   const float* __restrict__ d1,
                                   float* __restrict__ o)
{
    int i = blockIdx.x * blockDim.x + threadIdx.x;
    if (i < Bc * Hc) {
        o[i] = d0[i];
        o[Bc * Hc + i] = d1[i];
    }
}

// ---------------- host ----------------
extern "C" void kernel_launch(void* const* d_in, const int* in_sizes, int n_in,
                              void* d_out, int out_size)
{
    (void)in_sizes; (void)n_in; (void)out_size;
    const float* x     = (const float*)d_in[0];
    const float* emb   = (const float*)d_in[1];
    const float* eWih0 = (const float*)d_in[2];
    const float* eWhh0 = (const float*)d_in[3];
    const float* eb0   = (const float*)d_in[4];
    const float* eWih1 = (const float*)d_in[5];
    const float* eWhh1 = (const float*)d_in[6];
    const float* eb1   = (const float*)d_in[7];
    const float* dWih0 = (const float*)d_in[8];
    const float* dWhh0 = (const float*)d_in[9];
    const float* db0   = (const float*)d_in[10];
    const float* dWih1 = (const float*)d_in[11];
    const float* dWhh1 = (const float*)d_in[12];
    const float* db1   = (const float*)d_in[13];
    const float* fcW   = (const float*)d_in[14];
    const float* fcb   = (const float*)d_in[15];
    float* out = (float*)d_out;

    float *U0, *h0base, *h1base, *d0base, *d1base, *zero;
    int* tok;
    cudaGetSymbolAddress((void**)&U0, g_U0);
    cudaGetSymbolAddress((void**)&h0base, g_h0);
    cudaGetSymbolAddress((void**)&h1base, g_h1);
    cudaGetSymbolAddress((void**)&d0base, g_d0);
    cudaGetSymbolAddress((void**)&d1base, g_d1);
    cudaGetSymbolAddress((void**)&zero, g_zero);
    cudaGetSymbolAddress((void**)&tok, g_tok);

    float* h0b[2] = { h0base, h0base + (size_t)Bc * Hc };
    float* h1b[2] = { h1base, h1base + (size_t)Bc * Hc };
    float* d0b[2] = { d0base, d0base + (size_t)Bc * Hc };
    float* d1b[2] = { d1base, d1base + (size_t)Bc * Hc };

    init_kernel<<<(Bc * Hc + 255) / 256, 256>>>(zero, tok);

    // ---- precompute U0 = x_flat @ eWih0^T + b0 (high-intensity 8x8 config) ----
    {
        GemmJob j = {};
        j.A1 = x; j.lda1 = Lc; j.W1 = eWih0; j.K1 = Lc;
        j.gather = nullptr; j.A2 = nullptr;
        j.bias = eb0; j.addmat = nullptr; j.ldadd = 0;
        j.C = U0; j.ldc = Hc; j.act = 0; j.valid = 1;
        gemm_kernel<256, 128, 128, 8, 8>
            <<<dim3(Hc / 128, (Bc * Tc) / 128, 1), 256>>>(j, j);
    }

    // ---- encoder: launch L_t computes h0_t (job0) and h1_{t-1} (job1) ----
    for (int t = 0; t <= Tc; t++) {
        GemmJob j0 = {}, j1 = {};
        if (t < Tc) {
            j0.A1 = (t == 0) ? zero : h0b[(t - 1) & 1];
            j0.lda1 = Hc; j0.W1 = eWhh0; j0.K1 = Hc;
            j0.addmat = U0 + (size_t)t * Hc; j0.ldadd = (long)Tc * Hc;
            j0.C = h0b[t & 1]; j0.ldc = Hc; j0.act = 1; j0.valid = 1;
        }
        if (t >= 1) {
            int s = t - 1;
            j1.A1 = h0b[s & 1]; j1.lda1 = Hc; j1.W1 = eWih1; j1.K1 = Hc;
            j1.A2 = (s == 0) ? zero : h1b[(s - 1) & 1];
            j1.lda2 = Hc; j1.W2 = eWhh1; j1.K2 = Hc;
            j1.bias = eb1;
            j1.C = h1b[s & 1]; j1.ldc = Hc; j1.act = 1; j1.valid = 1;
        }
        gemm_kernel<256, 64, 64, 4, 4>
            <<<dim3(Hc / 64, Bc / 64, 2), 256>>>(j0, j1);
    }

    // ---- decoder: greedy autoregressive ----
    const float* d0prev = h0b[(Tc - 1) & 1];
    const float* d1prev = h1b[(Tc - 1) & 1];
    for (int s = 0; s < ML; s++) {
        float* d0cur = d0b[s & 1];
        float* d1cur = d1b[s & 1];
        {
            GemmJob j = {};
            j.A1 = emb; j.lda1 = Hc; j.W1 = dWih0; j.K1 = Hc;
            j.gather = tok;
            j.A2 = d0prev; j.lda2 = Hc; j.W2 = dWhh0; j.K2 = Hc;
            j.bias = db0;
            j.C = d0cur; j.ldc = Hc; j.act = 1; j.valid = 1;
            gemm_kernel<128, 32, 64, 4, 4>
                <<<dim3(Hc / 64, Bc / 32, 1), 128>>>(j, j);
        }
        {
            GemmJob j = {};
            j.A1 = d0cur; j.lda1 = Hc; j.W1 = dWih1; j.K1 = Hc;
            j.A2 = d1prev; j.lda2 = Hc; j.W2 = dWhh1; j.K2 = Hc;
            j.bias = db1;
            j.C = d1cur; j.ldc = Hc; j.act = 1; j.valid = 1;
            gemm_kernel<128, 32, 64, 4, 4>
                <<<dim3(Hc / 64, Bc / 32, 1), 128>>>(j, j);
        }
        logits_kernel<<<Bc, 256>>>(d1cur, fcW, fcb, out, s, tok);
        d0prev = d0cur;
        d1prev = d1cur;
    }

    copy_hidden_kernel<<<(Bc * Hc + 255) / 256, 256>>>(
        d0prev, d1prev, out + (size_t)Bc * Vc * ML);
}